// round 7
// baseline (speedup 1.0000x reference)
#include <cuda_runtime.h>
#include <cuda_bf16.h>
#include <mma.h>
#include <cstdint>

using namespace nvcuda;

#define NROWS_MAX 65536
typedef unsigned long long ull;

// scratch: left/right activations [n][0..31]=left, [n][32..63]=right
__device__ __align__(16) float g_lr[(size_t)NROWS_MAX * 64];
// pre-split Ws1 in bf16 hi/lo: [17 chunks][64 K][136 N(padded)]
#define BPAD 136
__device__ __align__(16) __nv_bfloat16 g_whi[17 * 64 * BPAD];
__device__ __align__(16) __nv_bfloat16 g_wlo[17 * 64 * BPAD];

// ---------- packed f32x2 helpers (k_lr) ----------
__device__ __forceinline__ ull pk2(float x) {
    ull r; asm("mov.b64 %0, {%1, %1};" : "=l"(r) : "f"(x)); return r;
}
__device__ __forceinline__ void fma2(ull &d, ull a, ull b) {
    asm("fma.rn.f32x2 %0, %1, %2, %0;" : "+l"(d) : "l"(a), "l"(b));
}
__device__ __forceinline__ ull mul2(ull a, ull b) {
    ull d; asm("mul.rn.f32x2 %0, %1, %2;" : "=l"(d) : "l"(a), "l"(b)); return d;
}
__device__ __forceinline__ float2 up2(ull v) {
    float2 f; asm("mov.b64 {%0, %1}, %2;" : "=f"(f.x), "=f"(f.y) : "l"(v)); return f;
}
// ---------- cp.async ----------
__device__ __forceinline__ uint32_t s2u(const void* p) {
    uint32_t a;
    asm("{ .reg .u64 t; cvta.to.shared.u64 t, %1; cvt.u32.u64 %0, t; }" : "=r"(a) : "l"(p));
    return a;
}
__device__ __forceinline__ void cpa16(uint32_t dst, const void* src) {
    asm volatile("cp.async.ca.shared.global [%0], [%1], 16;" :: "r"(dst), "l"(src));
}
__device__ __forceinline__ void cpa_commit() { asm volatile("cp.async.commit_group;"); }
template<int N> __device__ __forceinline__ void cpa_wait() {
    asm volatile("cp.async.wait_group %0;" :: "n"(N));
}

// =====================================================================
// Kernel 0: split Ws1 [1088][128] -> bf16 hi/lo, [17][64][136] padded
// =====================================================================
__global__ void k_conv(const float* __restrict__ Ws1) {
    int gid = blockIdx.x * 256 + threadIdx.x;
    if (gid >= 17 * 64 * BPAD) return;
    int s = gid / (64 * BPAD);
    int rem = gid % (64 * BPAD);
    int k = rem / BPAD, t = rem % BPAD;
    float w = (t < 128) ? Ws1[(s * 64 + k) * 128 + t] : 0.f;
    __nv_bfloat16 hi = __float2bfloat16(w);
    __nv_bfloat16 lo = __float2bfloat16(w - __bfloat162float(hi));
    g_whi[gid] = hi;
    g_wlo[gid] = lo;
}

// =====================================================================
// Kernel A: left = im(na, b) @ Wa + ba ; right = im(c, d) @ Wa + ba
// (unchanged FFMA2 path)
// =====================================================================
#define PADA 132
__global__ __launch_bounds__(128, 4) void k_lr(
    const float* __restrict__ concepts, const float* __restrict__ Wn,
    const float* __restrict__ bn, const float* __restrict__ Wa,
    const float* __restrict__ ba, const void* __restrict__ idxp,
    int nrows)
{
    __shared__ __align__(16) float uT[32 * PADA];
    __shared__ __align__(16) float vT[32 * PADA];
    __shared__ __align__(16) float Bs[3 * 1024];

    int tid  = threadIdx.x;
    int lane = tid & 31, w = tid >> 5;
    int nb128 = nrows >> 7;
    bool leftside = (blockIdx.x < (unsigned)nb128);
    int n0 = (leftside ? blockIdx.x : blockIdx.x - nb128) << 7;
    int cu_col = leftside ? 0 : 2;

    uint32_t bs_base = s2u(Bs);
    int e0 = tid * 2;
    #pragma unroll
    for (int p = 0; p < 2; ++p) {
        #pragma unroll
        for (int q = 0; q < 2; ++q)
            cpa16(bs_base + ((p % 3) * 1024 + (e0 + q) * 4) * 4,
                  Wa + (size_t)p * 1024 + (e0 + q) * 4);
        cpa_commit();
    }

    const int* idx32 = (const int*)idxp;
    bool is64 = (idx32[1] == 0) & (idx32[3] == 0) & (idx32[5] == 0) & (idx32[7] == 0);
    const long long* idx64 = (const long long*)idxp;

    for (int it = 0; it < 32; ++it) {
        int r = it * 4 + w;
        long long base = (long long)(n0 + r) * 4 + cu_col;
        long long cu = is64 ? idx64[base]     : (long long)idx32[base];
        long long cv = is64 ? idx64[base + 1] : (long long)idx32[base + 1];
        uT[lane * PADA + r] = concepts[cu * 32 + lane];
        vT[lane * PADA + r] = concepts[cv * 32 + lane];
    }
    __syncthreads();

    if (leftside) {
        float wn[32];
        #pragma unroll
        for (int i2 = 0; i2 < 32; ++i2) wn[i2] = Wn[i2 * 32 + lane];
        float bnk = bn[lane];
        for (int rr = 0; rr < 32; ++rr) {
            int r = (w << 5) + rr;
            float na = bnk;
            #pragma unroll
            for (int i2 = 0; i2 < 32; ++i2)
                na = fmaf(uT[i2 * PADA + r], wn[i2], na);
            __syncwarp();
            uT[lane * PADA + r] = na;
            __syncwarp();
        }
    }
    __syncthreads();

    int tc = tid & 7, tr = tid >> 3;
    int c0 = tc << 2, r0 = tr << 3;
    ull acc[4][4];
    #pragma unroll
    for (int p = 0; p < 4; ++p)
        #pragma unroll
        for (int c = 0; c < 4; ++c) acc[p][c] = 0ull;

    for (int s = 0; s < 34; ++s) {
        cpa_wait<1>();
        __syncthreads();
        if (s + 2 < 34) {
            #pragma unroll
            for (int q = 0; q < 2; ++q)
                cpa16(bs_base + (((s + 2) % 3) * 1024 + (e0 + q) * 4) * 4,
                      Wa + (size_t)(s + 2) * 1024 + (e0 + q) * 4);
        }
        cpa_commit();

        const float* Bc = Bs + (s % 3) * 1024;

        if (s >= 2) {
            int ii = s - 2;
            ull qa[4][4];
            #pragma unroll
            for (int kk = 0; kk < 32; ++kk) {
                float4 ra = *(const float4*)&vT[kk * PADA + r0];
                float4 rb = *(const float4*)&vT[kk * PADA + r0 + 4];
                ull rp[4] = { ((const ull*)&ra)[0], ((const ull*)&ra)[1],
                              ((const ull*)&rb)[0], ((const ull*)&rb)[1] };
                float4 bv = *(const float4*)&Bc[(kk << 5) + c0];
                ull bd[4] = { pk2(bv.x), pk2(bv.y), pk2(bv.z), pk2(bv.w) };
                if (kk == 0) {
                    #pragma unroll
                    for (int p = 0; p < 4; ++p)
                        #pragma unroll
                        for (int c = 0; c < 4; ++c)
                            qa[p][c] = mul2(rp[p], bd[c]);
                } else {
                    #pragma unroll
                    for (int p = 0; p < 4; ++p)
                        #pragma unroll
                        for (int c = 0; c < 4; ++c)
                            fma2(qa[p][c], rp[p], bd[c]);
                }
            }
            float4 ua = *(const float4*)&uT[ii * PADA + r0];
            float4 ub = *(const float4*)&uT[ii * PADA + r0 + 4];
            ull up[4] = { ((const ull*)&ua)[0], ((const ull*)&ua)[1],
                          ((const ull*)&ub)[0], ((const ull*)&ub)[1] };
            #pragma unroll
            for (int p = 0; p < 4; ++p)
                #pragma unroll
                for (int c = 0; c < 4; ++c)
                    fma2(acc[p][c], up[p], qa[p][c]);
        } else {
            const float* S = (s == 0) ? uT : vT;
            #pragma unroll
            for (int kk = 0; kk < 32; ++kk) {
                float4 ra = *(const float4*)&S[kk * PADA + r0];
                float4 rb = *(const float4*)&S[kk * PADA + r0 + 4];
                ull rp[4] = { ((const ull*)&ra)[0], ((const ull*)&ra)[1],
                              ((const ull*)&rb)[0], ((const ull*)&rb)[1] };
                float4 bv = *(const float4*)&Bc[(kk << 5) + c0];
                ull bd[4] = { pk2(bv.x), pk2(bv.y), pk2(bv.z), pk2(bv.w) };
                #pragma unroll
                for (int p = 0; p < 4; ++p)
                    #pragma unroll
                    for (int c = 0; c < 4; ++c)
                        fma2(acc[p][c], rp[p], bd[c]);
            }
        }
    }

    float4 bav = *(const float4*)&ba[c0];
    int hoff = leftside ? 0 : 32;
    #pragma unroll
    for (int p = 0; p < 4; ++p) {
        float2 v0 = up2(acc[p][0]);
        float2 v1 = up2(acc[p][1]);
        float2 v2 = up2(acc[p][2]);
        float2 v3 = up2(acc[p][3]);
        float4 oA = { v0.x + bav.x, v1.x + bav.y, v2.x + bav.z, v3.x + bav.w };
        float4 oB = { v0.y + bav.x, v1.y + bav.y, v2.y + bav.z, v3.y + bav.w };
        *(float4*)&g_lr[(size_t)(n0 + r0 + 2 * p)     * 64 + hoff + c0] = oA;
        *(float4*)&g_lr[(size_t)(n0 + r0 + 2 * p + 1) * 64 + hoff + c0] = oB;
    }
}

// =====================================================================
// Kernel B (wmma/HMMA): per 128-row tile, D[128x128] = F[128x1088] @ Ws1
// via bf16 hi/lo split (3 passes), K chunked by 64, B triple-buffered.
// Epilogue: +bs1, elu, dot Ws2.
// =====================================================================
#define SM_LR   0                      // float[128*64]        32768
#define SM_AHI  32768                  // bf16[128][136]       34816
#define SM_ALO  67584                  // bf16[128][136]       34816
#define SM_B    102400                 // 3 x (hi 17408 + lo 17408)
#define SM_BS1  206848                 // float[128]
#define SM_W2   207360                 // float[128]
#define KM_SMEM 207872

__global__ __launch_bounds__(256, 1) void k_main(
    const float* __restrict__ bs1, const float* __restrict__ Ws2,
    const float* __restrict__ bs2, float* __restrict__ out)
{
    extern __shared__ __align__(16) char sm[];
    float* LR = (float*)(sm + SM_LR);
    __nv_bfloat16* Ahi = (__nv_bfloat16*)(sm + SM_AHI);
    __nv_bfloat16* Alo = (__nv_bfloat16*)(sm + SM_ALO);
    uint32_t sb = s2u(sm);
    int tid = threadIdx.x;
    int wid = tid >> 5;
    int n0 = blockIdx.x << 7;

    // prefetch B chunks 0,1 (hi+lo, 17408 B each = 1088 x 16B)
    #pragma unroll
    for (int p = 0; p < 2; ++p) {
        for (int e = tid; e < 1088; e += 256) {
            cpa16(sb + SM_B + p * 34816 + e * 16, (const char*)g_whi + (size_t)p * 17408 + e * 16);
            cpa16(sb + SM_B + p * 34816 + 17408 + e * 16, (const char*)g_wlo + (size_t)p * 17408 + e * 16);
        }
        cpa_commit();
    }

    // load L/R rows and epilogue vectors
    #pragma unroll
    for (int it = 0; it < 8; ++it) {
        int e4 = it * 256 + tid;                 // 2048 float4s
        int r = e4 >> 4, q = e4 & 15;
        *(float4*)&LR[r * 64 + q * 4] = *(const float4*)&g_lr[(size_t)(n0 + r) * 64 + q * 4];
    }
    if (tid < 128) {
        ((float*)(sm + SM_BS1))[tid] = bs1[tid];
        ((float*)(sm + SM_W2))[tid]  = Ws2[tid];
    }
    __syncthreads();

    wmma::fragment<wmma::accumulator, 16, 16, 16, float> acc[8];
    #pragma unroll
    for (int nt = 0; nt < 8; ++nt) wmma::fill_fragment(acc[nt], 0.f);

    for (int s = 0; s < 17; ++s) {
        // materialize feature chunk s into A (prev chunk's compute done at loop-end sync)
        #pragma unroll
        for (int it = 0; it < 32; ++it) {
            int e = it * 256 + tid;              // 8192 features
            int row = e >> 6, t = e & 63;
            float f;
            if (s == 0) {
                f = LR[row * 64 + t];            // [L | R]
            } else {
                int i = 2 * (s - 1) + (t >> 5), j = t & 31;
                f = LR[row * 64 + i] * LR[row * 64 + 32 + j];
            }
            __nv_bfloat16 h = __float2bfloat16(f);
            __nv_bfloat16 l = __float2bfloat16(f - __bfloat162float(h));
            Ahi[row * BPAD + t] = h;
            Alo[row * BPAD + t] = l;
        }
        cpa_wait<1>();                           // B chunk s arrived
        __syncthreads();                         // A visible + B visible

        if (s + 2 < 17) {                        // prefetch into buffer freed last iter
            for (int e = tid; e < 1088; e += 256) {
                cpa16(sb + SM_B + ((s + 2) % 3) * 34816 + e * 16,
                      (const char*)g_whi + (size_t)(s + 2) * 17408 + e * 16);
                cpa16(sb + SM_B + ((s + 2) % 3) * 34816 + 17408 + e * 16,
                      (const char*)g_wlo + (size_t)(s + 2) * 17408 + e * 16);
            }
        }
        cpa_commit();

        const __nv_bfloat16* Bhi = (const __nv_bfloat16*)(sm + SM_B + (s % 3) * 34816);
        const __nv_bfloat16* Blo = Bhi + 8704;

        #pragma unroll
        for (int ks = 0; ks < 4; ++ks) {
            wmma::fragment<wmma::matrix_a, 16, 16, 16, __nv_bfloat16, wmma::row_major> ah, al;
            wmma::load_matrix_sync(ah, Ahi + wid * 16 * BPAD + ks * 16, BPAD);
            wmma::load_matrix_sync(al, Alo + wid * 16 * BPAD + ks * 16, BPAD);
            #pragma unroll
            for (int nt = 0; nt < 8; ++nt) {
                wmma::fragment<wmma::matrix_b, 16, 16, 16, __nv_bfloat16, wmma::row_major> bh, bl;
                wmma::load_matrix_sync(bh, Bhi + ks * 16 * BPAD + nt * 16, BPAD);
                wmma::load_matrix_sync(bl, Blo + ks * 16 * BPAD + nt * 16, BPAD);
                wmma::mma_sync(acc[nt], ah, bh, acc[nt]);
                wmma::mma_sync(acc[nt], ah, bl, acc[nt]);
                wmma::mma_sync(acc[nt], al, bh, acc[nt]);
            }
        }
        __syncthreads();                         // A consumed; next iter may overwrite
    }

    // epilogue: D -> smem (reuse A region), +bs1, elu, dot Ws2
    float* D = (float*)(sm + SM_AHI);            // 128 x 136 f32 = 69632 B (fits A hi+lo)
    #pragma unroll
    for (int nt = 0; nt < 8; ++nt)
        wmma::store_matrix_sync(D + wid * 16 * BPAD + nt * 16, acc[nt], BPAD, wmma::mem_row_major);
    __syncthreads();

    {
        int row = tid >> 1, hf = tid & 1;
        const float* bs1s = (const float*)(sm + SM_BS1);
        const float* w2s  = (const float*)(sm + SM_W2);
        float a = 0.f;
        #pragma unroll
        for (int c0 = hf * 64, c = 0; c < 64; ++c) {
            float x = D[row * BPAD + c0 + c] + bs1s[c0 + c];
            float h = x > 0.f ? x : expm1f(x);
            a = fmaf(h, w2s[c0 + c], a);
        }
        a += __shfl_xor_sync(0xffffffffu, a, 1);
        if (hf == 0) out[n0 + row] = a + bs2[0];
    }
}

extern "C" void kernel_launch(void* const* d_in, const int* in_sizes, int n_in,
                              void* d_out, int out_size)
{
    const float* concepts = (const float*)d_in[0];
    const float* Wn  = (const float*)d_in[1];
    const float* bn  = (const float*)d_in[2];
    const float* Wa  = (const float*)d_in[3];
    const float* ba  = (const float*)d_in[4];
    const float* Ws1 = (const float*)d_in[5];
    const float* bs1 = (const float*)d_in[6];
    const float* Ws2 = (const float*)d_in[7];
    const float* bs2 = (const float*)d_in[8];
    const void*  idx = d_in[9];
    int nrows = in_sizes[9] / 4;

    static int inited = 0;
    if (!inited) {
        cudaFuncSetAttribute(k_main, cudaFuncAttributeMaxDynamicSharedMemorySize, KM_SMEM);
        inited = 1;
    }

    k_conv<<<(17 * 64 * BPAD + 255) / 256, 256>>>(Ws1);
    k_lr<<<(nrows / 128) * 2, 128>>>(concepts, Wn, bn, Wa, ba, idx, nrows);
    k_main<<<nrows / 128, 256, KM_SMEM>>>(bs1, Ws2, bs2, (float*)d_out);
}

// round 8
// speedup vs baseline: 1.3619x; 1.3619x over previous
#include <cuda_runtime.h>
#include <cuda_bf16.h>
#include <cstdint>

#define NROWS_MAX 65536
typedef unsigned long long ull;

// scratch: left/right activations [n][0..31]=left, [n][32..63]=right
__device__ __align__(16) float g_lr[(size_t)NROWS_MAX * 64];
// pre-split Ws1, bf16, N-major, XOR-swizzled: [17 chunks][128 n][64 k]
__device__ __align__(16) __nv_bfloat16 g_whi[17 * 8192];
__device__ __align__(16) __nv_bfloat16 g_wlo[17 * 8192];

// ---------- packed f32x2 helpers (k_lr) ----------
__device__ __forceinline__ ull pk2(float x) {
    ull r; asm("mov.b64 %0, {%1, %1};" : "=l"(r) : "f"(x)); return r;
}
__device__ __forceinline__ void fma2(ull &d, ull a, ull b) {
    asm("fma.rn.f32x2 %0, %1, %2, %0;" : "+l"(d) : "l"(a), "l"(b));
}
__device__ __forceinline__ ull mul2(ull a, ull b) {
    ull d; asm("mul.rn.f32x2 %0, %1, %2;" : "=l"(d) : "l"(a), "l"(b)); return d;
}
__device__ __forceinline__ float2 up2(ull v) {
    float2 f; asm("mov.b64 {%0, %1}, %2;" : "=f"(f.x), "=f"(f.y) : "l"(v)); return f;
}
// ---------- cp.async ----------
__device__ __forceinline__ uint32_t s2u(const void* p) {
    uint32_t a;
    asm("{ .reg .u64 t; cvta.to.shared.u64 t, %1; cvt.u32.u64 %0, t; }" : "=r"(a) : "l"(p));
    return a;
}
__device__ __forceinline__ void cpa16(uint32_t dst, const void* src) {
    asm volatile("cp.async.ca.shared.global [%0], [%1], 16;" :: "r"(dst), "l"(src));
}
__device__ __forceinline__ void cpa_commit() { asm volatile("cp.async.commit_group;"); }
template<int N> __device__ __forceinline__ void cpa_wait() {
    asm volatile("cp.async.wait_group %0;" :: "n"(N));
}
// ---------- tensor primitives ----------
__device__ __forceinline__ void ldsm4(uint32_t* r, uint32_t a) {
    asm volatile("ldmatrix.sync.aligned.m8n8.x4.shared.b16 {%0,%1,%2,%3}, [%4];"
        : "=r"(r[0]), "=r"(r[1]), "=r"(r[2]), "=r"(r[3]) : "r"(a));
}
__device__ __forceinline__ void ldsm2(uint32_t* r, uint32_t a) {
    asm volatile("ldmatrix.sync.aligned.m8n8.x2.shared.b16 {%0,%1}, [%2];"
        : "=r"(r[0]), "=r"(r[1]) : "r"(a));
}
__device__ __forceinline__ void mma_bf16(float* d, const uint32_t* a, const uint32_t* b) {
    asm volatile("mma.sync.aligned.m16n8k16.row.col.f32.bf16.bf16.f32 "
        "{%0,%1,%2,%3}, {%4,%5,%6,%7}, {%8,%9}, {%0,%1,%2,%3};"
        : "+f"(d[0]), "+f"(d[1]), "+f"(d[2]), "+f"(d[3])
        : "r"(a[0]), "r"(a[1]), "r"(a[2]), "r"(a[3]), "r"(b[0]), "r"(b[1]));
}

// =====================================================================
// Kernel 0: split Ws1 [1088][128] -> bf16 hi/lo, N-major swizzled
// element (s, k, n) -> chunk s, byte n*128 + ((k>>3 ^ (n&7))<<4) + (k&7)*2
// =====================================================================
__global__ void k_conv(const float* __restrict__ Ws1) {
    int gid = blockIdx.x * 256 + threadIdx.x;
    if (gid >= 17 * 64 * 128) return;
    int s = gid >> 13, rem = gid & 8191;
    int k = rem >> 7, n = rem & 127;
    float w = Ws1[(s * 64 + k) * 128 + n];
    __nv_bfloat16 hi = __float2bfloat16(w);
    __nv_bfloat16 lo = __float2bfloat16(w - __bfloat162float(hi));
    uint32_t off = (uint32_t)s * 16384 + n * 128 + ((((k >> 3) ^ (n & 7))) << 4) + (k & 7) * 2;
    *(__nv_bfloat16*)((char*)g_whi + off) = hi;
    *(__nv_bfloat16*)((char*)g_wlo + off) = lo;
}

// =====================================================================
// Kernel A: left/right = im(..) @ Wa + ba  (proven FFMA2 path, unchanged)
// =====================================================================
#define PADA 132
__global__ __launch_bounds__(128, 4) void k_lr(
    const float* __restrict__ concepts, const float* __restrict__ Wn,
    const float* __restrict__ bn, const float* __restrict__ Wa,
    const float* __restrict__ ba, const void* __restrict__ idxp,
    int nrows)
{
    __shared__ __align__(16) float uT[32 * PADA];
    __shared__ __align__(16) float vT[32 * PADA];
    __shared__ __align__(16) float Bs[3 * 1024];

    int tid  = threadIdx.x;
    int lane = tid & 31, w = tid >> 5;
    int nb128 = nrows >> 7;
    bool leftside = (blockIdx.x < (unsigned)nb128);
    int n0 = (leftside ? blockIdx.x : blockIdx.x - nb128) << 7;
    int cu_col = leftside ? 0 : 2;

    uint32_t bs_base = s2u(Bs);
    int e0 = tid * 2;
    #pragma unroll
    for (int p = 0; p < 2; ++p) {
        #pragma unroll
        for (int q = 0; q < 2; ++q)
            cpa16(bs_base + ((p % 3) * 1024 + (e0 + q) * 4) * 4,
                  Wa + (size_t)p * 1024 + (e0 + q) * 4);
        cpa_commit();
    }

    const int* idx32 = (const int*)idxp;
    bool is64 = (idx32[1] == 0) & (idx32[3] == 0) & (idx32[5] == 0) & (idx32[7] == 0);
    const long long* idx64 = (const long long*)idxp;

    for (int it = 0; it < 32; ++it) {
        int r = it * 4 + w;
        long long base = (long long)(n0 + r) * 4 + cu_col;
        long long cu = is64 ? idx64[base]     : (long long)idx32[base];
        long long cv = is64 ? idx64[base + 1] : (long long)idx32[base + 1];
        uT[lane * PADA + r] = concepts[cu * 32 + lane];
        vT[lane * PADA + r] = concepts[cv * 32 + lane];
    }
    __syncthreads();

    if (leftside) {
        float wn[32];
        #pragma unroll
        for (int i2 = 0; i2 < 32; ++i2) wn[i2] = Wn[i2 * 32 + lane];
        float bnk = bn[lane];
        for (int rr = 0; rr < 32; ++rr) {
            int r = (w << 5) + rr;
            float na = bnk;
            #pragma unroll
            for (int i2 = 0; i2 < 32; ++i2)
                na = fmaf(uT[i2 * PADA + r], wn[i2], na);
            __syncwarp();
            uT[lane * PADA + r] = na;
            __syncwarp();
        }
    }
    __syncthreads();

    int tc = tid & 7, tr = tid >> 3;
    int c0 = tc << 2, r0 = tr << 3;
    ull acc[4][4];
    #pragma unroll
    for (int p = 0; p < 4; ++p)
        #pragma unroll
        for (int c = 0; c < 4; ++c) acc[p][c] = 0ull;

    for (int s = 0; s < 34; ++s) {
        cpa_wait<1>();
        __syncthreads();
        if (s + 2 < 34) {
            #pragma unroll
            for (int q = 0; q < 2; ++q)
                cpa16(bs_base + (((s + 2) % 3) * 1024 + (e0 + q) * 4) * 4,
                      Wa + (size_t)(s + 2) * 1024 + (e0 + q) * 4);
        }
        cpa_commit();

        const float* Bc = Bs + (s % 3) * 1024;

        if (s >= 2) {
            int ii = s - 2;
            ull qa[4][4];
            #pragma unroll
            for (int kk = 0; kk < 32; ++kk) {
                float4 ra = *(const float4*)&vT[kk * PADA + r0];
                float4 rb = *(const float4*)&vT[kk * PADA + r0 + 4];
                ull rp[4] = { ((const ull*)&ra)[0], ((const ull*)&ra)[1],
                              ((const ull*)&rb)[0], ((const ull*)&rb)[1] };
                float4 bv = *(const float4*)&Bc[(kk << 5) + c0];
                ull bd[4] = { pk2(bv.x), pk2(bv.y), pk2(bv.z), pk2(bv.w) };
                if (kk == 0) {
                    #pragma unroll
                    for (int p = 0; p < 4; ++p)
                        #pragma unroll
                        for (int c = 0; c < 4; ++c)
                            qa[p][c] = mul2(rp[p], bd[c]);
                } else {
                    #pragma unroll
                    for (int p = 0; p < 4; ++p)
                        #pragma unroll
                        for (int c = 0; c < 4; ++c)
                            fma2(qa[p][c], rp[p], bd[c]);
                }
            }
            float4 ua = *(const float4*)&uT[ii * PADA + r0];
            float4 ub = *(const float4*)&uT[ii * PADA + r0 + 4];
            ull up[4] = { ((const ull*)&ua)[0], ((const ull*)&ua)[1],
                          ((const ull*)&ub)[0], ((const ull*)&ub)[1] };
            #pragma unroll
            for (int p = 0; p < 4; ++p)
                #pragma unroll
                for (int c = 0; c < 4; ++c)
                    fma2(acc[p][c], up[p], qa[p][c]);
        } else {
            const float* S = (s == 0) ? uT : vT;
            #pragma unroll
            for (int kk = 0; kk < 32; ++kk) {
                float4 ra = *(const float4*)&S[kk * PADA + r0];
                float4 rb = *(const float4*)&S[kk * PADA + r0 + 4];
                ull rp[4] = { ((const ull*)&ra)[0], ((const ull*)&ra)[1],
                              ((const ull*)&rb)[0], ((const ull*)&rb)[1] };
                float4 bv = *(const float4*)&Bc[(kk << 5) + c0];
                ull bd[4] = { pk2(bv.x), pk2(bv.y), pk2(bv.z), pk2(bv.w) };
                #pragma unroll
                for (int p = 0; p < 4; ++p)
                    #pragma unroll
                    for (int c = 0; c < 4; ++c)
                        fma2(acc[p][c], rp[p], bd[c]);
            }
        }
    }

    float4 bav = *(const float4*)&ba[c0];
    int hoff = leftside ? 0 : 32;
    #pragma unroll
    for (int p = 0; p < 4; ++p) {
        float2 v0 = up2(acc[p][0]);
        float2 v1 = up2(acc[p][1]);
        float2 v2 = up2(acc[p][2]);
        float2 v3 = up2(acc[p][3]);
        float4 oA = { v0.x + bav.x, v1.x + bav.y, v2.x + bav.z, v3.x + bav.w };
        float4 oB = { v0.y + bav.x, v1.y + bav.y, v2.y + bav.z, v3.y + bav.w };
        *(float4*)&g_lr[(size_t)(n0 + r0 + 2 * p)     * 64 + hoff + c0] = oA;
        *(float4*)&g_lr[(size_t)(n0 + r0 + 2 * p + 1) * 64 + hoff + c0] = oB;
    }
}

// =====================================================================
// Kernel B: raw mma.sync bf16 hi/lo split. 128 rows x 128 cols per CTA.
// Warp grid 2M x 4N; warp tile 64x32 (4 mtiles x 4 ntiles m16n8k16).
// =====================================================================
#define SM_LR   0             // float[128*64]                    32768
#define SM_AHI  32768         // bf16[128][64] swizzled           16384
#define SM_ALO  49152         // bf16[128][64] swizzled           16384
#define SM_B    65536         // 3 x (hi 16384 + lo 16384)        98304
#define SM_BS1  163840        // float[128]
#define SM_W2   164352        // float[128]
#define SM_DS   164864        // float[128][4]
#define KM_SMEM 166912

__global__ __launch_bounds__(256, 1) void k_main(
    const float* __restrict__ bs1, const float* __restrict__ Ws2,
    const float* __restrict__ bs2, float* __restrict__ out)
{
    extern __shared__ __align__(16) char sm[];
    float* LR = (float*)(sm + SM_LR);
    uint32_t sb = s2u(sm);
    int tid = threadIdx.x;
    int wid = tid >> 5, lane = tid & 31;
    int n0 = blockIdx.x << 7;

    // prefetch B chunks 0,1 (32KB each: 2048 x 16B)
    #pragma unroll
    for (int p = 0; p < 2; ++p) {
        #pragma unroll
        for (int q = 0; q < 4; ++q) {
            int e = q * 256 + tid;   // 1024 per half
            cpa16(sb + SM_B + p * 32768 + e * 16,         (const char*)g_whi + (size_t)p * 16384 + e * 16);
            cpa16(sb + SM_B + p * 32768 + 16384 + e * 16, (const char*)g_wlo + (size_t)p * 16384 + e * 16);
        }
        cpa_commit();
    }

    #pragma unroll
    for (int it = 0; it < 8; ++it) {
        int e4 = it * 256 + tid;
        int r = e4 >> 4, q = e4 & 15;
        *(float4*)&LR[r * 64 + q * 4] = *(const float4*)&g_lr[(size_t)(n0 + r) * 64 + q * 4];
    }
    if (tid < 128) {
        ((float*)(sm + SM_BS1))[tid] = bs1[tid];
        ((float*)(sm + SM_W2))[tid]  = Ws2[tid];
    }
    __syncthreads();

    float acc[4][4][4];
    #pragma unroll
    for (int mt = 0; mt < 4; ++mt)
        #pragma unroll
        for (int nt = 0; nt < 4; ++nt)
            #pragma unroll
            for (int e = 0; e < 4; ++e) acc[mt][nt][e] = 0.f;

    int m0w = (wid >> 2) * 64, n0w = (wid & 3) * 32;
    // ldmatrix lane geometry
    int li = lane & 7, lt = lane >> 3;           // A x4: tile lt
    int rA_off = li + ((lt & 1) << 3);           // row within 16-row tile
    int segA_h = lt >> 1;                        // k-seg half
    int hB = (lane >> 3) & 1;                    // B x2: k-seg half

    for (int s = 0; s < 17; ++s) {
        // materialize feature chunk s into Ahi/Alo (pairs; swizzled)
        #pragma unroll
        for (int it = 0; it < 16; ++it) {
            int p = it * 256 + tid;              // 4096 pairs
            int row = p >> 5, t0 = (p & 31) * 2;
            float f0, f1;
            if (s == 0) {
                f0 = LR[row * 64 + t0];
                f1 = LR[row * 64 + t0 + 1];
            } else {
                int i = 2 * (s - 1) + (t0 >> 5), j = t0 & 31;
                float Lv = LR[row * 64 + i];
                f0 = Lv * LR[row * 64 + 32 + j];
                f1 = Lv * LR[row * 64 + 32 + j + 1];
            }
            __nv_bfloat16 h0 = __float2bfloat16(f0);
            __nv_bfloat16 h1 = __float2bfloat16(f1);
            __nv_bfloat16 l0 = __float2bfloat16(f0 - __bfloat162float(h0));
            __nv_bfloat16 l1 = __float2bfloat16(f1 - __bfloat162float(h1));
            uint32_t wh = (uint32_t)__bfloat16_as_ushort(h0) | ((uint32_t)__bfloat16_as_ushort(h1) << 16);
            uint32_t wl = (uint32_t)__bfloat16_as_ushort(l0) | ((uint32_t)__bfloat16_as_ushort(l1) << 16);
            uint32_t off = row * 128 + ((((t0 >> 3) ^ (row & 7))) << 4) + (t0 & 7) * 2;
            *(uint32_t*)(sm + SM_AHI + off) = wh;
            *(uint32_t*)(sm + SM_ALO + off) = wl;
        }
        cpa_wait<1>();
        __syncthreads();                         // A visible + B chunk s visible

        if (s + 2 < 17) {
            #pragma unroll
            for (int q = 0; q < 4; ++q) {
                int e = q * 256 + tid;
                cpa16(sb + SM_B + ((s + 2) % 3) * 32768 + e * 16,
                      (const char*)g_whi + (size_t)(s + 2) * 16384 + e * 16);
                cpa16(sb + SM_B + ((s + 2) % 3) * 32768 + 16384 + e * 16,
                      (const char*)g_wlo + (size_t)(s + 2) * 16384 + e * 16);
            }
        }
        cpa_commit();

        uint32_t Bhi_b = sb + SM_B + (s % 3) * 32768;
        #pragma unroll
        for (int ks = 0; ks < 4; ++ks) {
            uint32_t bh[4][2], bl[4][2];
            #pragma unroll
            for (int nt = 0; nt < 4; ++nt) {
                int row = n0w + nt * 8 + li;
                uint32_t addr = Bhi_b + row * 128 + ((((2 * ks + hB) ^ (row & 7))) << 4);
                ldsm2(bh[nt], addr);
                ldsm2(bl[nt], addr + 16384);
            }
            #pragma unroll
            for (int mt = 0; mt < 4; ++mt) {
                int row = m0w + mt * 16 + rA_off;
                int seg = 2 * ks + segA_h;
                uint32_t addr = sb + SM_AHI + row * 128 + (((seg ^ (row & 7))) << 4);
                uint32_t ah[4], al[4];
                ldsm4(ah, addr);
                ldsm4(al, addr + 16384);
                #pragma unroll
                for (int nt = 0; nt < 4; ++nt) {
                    mma_bf16(acc[mt][nt], ah, bh[nt]);
                    mma_bf16(acc[mt][nt], ah, bl[nt]);
                    mma_bf16(acc[mt][nt], al, bh[nt]);
                }
            }
        }
        __syncthreads();                         // A consumed; safe to overwrite
    }

    // epilogue: +bs1, elu, dot Ws2, reduce
    const float* bs1s = (const float*)(sm + SM_BS1);
    const float* w2s  = (const float*)(sm + SM_W2);
    float* Dsum = (float*)(sm + SM_DS);
    int q = lane >> 2, c2 = (lane & 3) * 2;
    float bias2 = bs2[0];
    #pragma unroll
    for (int mt = 0; mt < 4; ++mt) {
        float s0 = 0.f, s1 = 0.f;
        #pragma unroll
        for (int nt = 0; nt < 4; ++nt) {
            int col = n0w + nt * 8 + c2;
            float2 bv = *(const float2*)&bs1s[col];
            float2 wv = *(const float2*)&w2s[col];
            float* d = acc[mt][nt];
            float x0 = d[0] + bv.x, x1 = d[1] + bv.y;
            float x2 = d[2] + bv.x, x3 = d[3] + bv.y;
            float h0 = x0 > 0.f ? x0 : expm1f(x0);
            float h1 = x1 > 0.f ? x1 : expm1f(x1);
            float h2 = x2 > 0.f ? x2 : expm1f(x2);
            float h3 = x3 > 0.f ? x3 : expm1f(x3);
            s0 = fmaf(h0, wv.x, fmaf(h1, wv.y, s0));
            s1 = fmaf(h2, wv.x, fmaf(h3, wv.y, s1));
        }
        s0 += __shfl_xor_sync(0xffffffffu, s0, 1);
        s0 += __shfl_xor_sync(0xffffffffu, s0, 2);
        s1 += __shfl_xor_sync(0xffffffffu, s1, 1);
        s1 += __shfl_xor_sync(0xffffffffu, s1, 2);
        if ((lane & 3) == 0) {
            int row = m0w + mt * 16 + q;
            Dsum[row * 4 + (wid & 3)] = s0;
            Dsum[(row + 8) * 4 + (wid & 3)] = s1;
        }
    }
    __syncthreads();
    if (tid < 128) {
        float v = Dsum[tid * 4] + Dsum[tid * 4 + 1] + Dsum[tid * 4 + 2] + Dsum[tid * 4 + 3];
        out[n0 + tid] = v + bias2;
    }
}

extern "C" void kernel_launch(void* const* d_in, const int* in_sizes, int n_in,
                              void* d_out, int out_size)
{
    const float* concepts = (const float*)d_in[0];
    const float* Wn  = (const float*)d_in[1];
    const float* bn  = (const float*)d_in[2];
    const float* Wa  = (const float*)d_in[3];
    const float* ba  = (const float*)d_in[4];
    const float* Ws1 = (const float*)d_in[5];
    const float* bs1 = (const float*)d_in[6];
    const float* Ws2 = (const float*)d_in[7];
    const float* bs2 = (const float*)d_in[8];
    const void*  idx = d_in[9];
    int nrows = in_sizes[9] / 4;

    static int inited = 0;
    if (!inited) {
        cudaFuncSetAttribute(k_main, cudaFuncAttributeMaxDynamicSharedMemorySize, KM_SMEM);
        inited = 1;
    }

    k_conv<<<(17 * 64 * 128 + 255) / 256, 256>>>(Ws1);
    k_lr<<<(nrows / 128) * 2, 128>>>(concepts, Wn, bn, Wa, ba, idx, nrows);
    k_main<<<nrows / 128, 256, KM_SMEM>>>(bs1, Ws2, bs2, (float*)d_out);
}

// round 9
// speedup vs baseline: 1.5542x; 1.1412x over previous
#include <cuda_runtime.h>
#include <cuda_bf16.h>
#include <cstdint>

#define NROWS_MAX 65536
typedef unsigned long long ull;

// scratch: left/right activations [n][0..31]=left, [n][32..63]=right
__device__ __align__(16) float g_lr[(size_t)NROWS_MAX * 64];
// pre-split Ws1, bf16, N-major, XOR-swizzled: [17 chunks][128 n][64 k]
__device__ __align__(16) __nv_bfloat16 g_whi[17 * 8192];
__device__ __align__(16) __nv_bfloat16 g_wlo[17 * 8192];

// ---------- packed f32x2 helpers (k_lr) ----------
__device__ __forceinline__ ull pk2(float x) {
    ull r; asm("mov.b64 %0, {%1, %1};" : "=l"(r) : "f"(x)); return r;
}
__device__ __forceinline__ void fma2(ull &d, ull a, ull b) {
    asm("fma.rn.f32x2 %0, %1, %2, %0;" : "+l"(d) : "l"(a), "l"(b));
}
__device__ __forceinline__ ull mul2(ull a, ull b) {
    ull d; asm("mul.rn.f32x2 %0, %1, %2;" : "=l"(d) : "l"(a), "l"(b)); return d;
}
__device__ __forceinline__ float2 up2(ull v) {
    float2 f; asm("mov.b64 {%0, %1}, %2;" : "=f"(f.x), "=f"(f.y) : "l"(v)); return f;
}
// ---------- cp.async ----------
__device__ __forceinline__ uint32_t s2u(const void* p) {
    uint32_t a;
    asm("{ .reg .u64 t; cvta.to.shared.u64 t, %1; cvt.u32.u64 %0, t; }" : "=r"(a) : "l"(p));
    return a;
}
__device__ __forceinline__ void cpa16(uint32_t dst, const void* src) {
    asm volatile("cp.async.ca.shared.global [%0], [%1], 16;" :: "r"(dst), "l"(src));
}
__device__ __forceinline__ void cpa_commit() { asm volatile("cp.async.commit_group;"); }
template<int N> __device__ __forceinline__ void cpa_wait() {
    asm volatile("cp.async.wait_group %0;" :: "n"(N));
}
// ---------- tensor primitives ----------
__device__ __forceinline__ void ldsm4(uint32_t* r, uint32_t a) {
    asm volatile("ldmatrix.sync.aligned.m8n8.x4.shared.b16 {%0,%1,%2,%3}, [%4];"
        : "=r"(r[0]), "=r"(r[1]), "=r"(r[2]), "=r"(r[3]) : "r"(a));
}
__device__ __forceinline__ void mma_bf16(float* d, const uint32_t* a, const uint32_t* b) {
    asm volatile("mma.sync.aligned.m16n8k16.row.col.f32.bf16.bf16.f32 "
        "{%0,%1,%2,%3}, {%4,%5,%6,%7}, {%8,%9}, {%0,%1,%2,%3};"
        : "+f"(d[0]), "+f"(d[1]), "+f"(d[2]), "+f"(d[3])
        : "r"(a[0]), "r"(a[1]), "r"(a[2]), "r"(a[3]), "r"(b[0]), "r"(b[1]));
}

// =====================================================================
// Kernel 0: split Ws1 [1088][128] -> bf16 hi/lo, N-major swizzled
// =====================================================================
__global__ void k_conv(const float* __restrict__ Ws1) {
    int gid = blockIdx.x * 256 + threadIdx.x;
    if (gid >= 17 * 64 * 128) return;
    int s = gid >> 13, rem = gid & 8191;
    int k = rem >> 7, n = rem & 127;
    float w = Ws1[(s * 64 + k) * 128 + n];
    __nv_bfloat16 hi = __float2bfloat16(w);
    __nv_bfloat16 lo = __float2bfloat16(w - __bfloat162float(hi));
    uint32_t off = (uint32_t)s * 16384 + n * 128 + ((((k >> 3) ^ (n & 7))) << 4) + (k & 7) * 2;
    *(__nv_bfloat16*)((char*)g_whi + off) = hi;
    *(__nv_bfloat16*)((char*)g_wlo + off) = lo;
}

// =====================================================================
// Kernel A: left/right = im(..) @ Wa + ba  (proven FFMA2 path, unchanged)
// =====================================================================
#define PADA 132
__global__ __launch_bounds__(128, 4) void k_lr(
    const float* __restrict__ concepts, const float* __restrict__ Wn,
    const float* __restrict__ bn, const float* __restrict__ Wa,
    const float* __restrict__ ba, const void* __restrict__ idxp,
    int nrows)
{
    __shared__ __align__(16) float uT[32 * PADA];
    __shared__ __align__(16) float vT[32 * PADA];
    __shared__ __align__(16) float Bs[3 * 1024];

    int tid  = threadIdx.x;
    int lane = tid & 31, w = tid >> 5;
    int nb128 = nrows >> 7;
    bool leftside = (blockIdx.x < (unsigned)nb128);
    int n0 = (leftside ? blockIdx.x : blockIdx.x - nb128) << 7;
    int cu_col = leftside ? 0 : 2;

    uint32_t bs_base = s2u(Bs);
    int e0 = tid * 2;
    #pragma unroll
    for (int p = 0; p < 2; ++p) {
        #pragma unroll
        for (int q = 0; q < 2; ++q)
            cpa16(bs_base + ((p % 3) * 1024 + (e0 + q) * 4) * 4,
                  Wa + (size_t)p * 1024 + (e0 + q) * 4);
        cpa_commit();
    }

    const int* idx32 = (const int*)idxp;
    bool is64 = (idx32[1] == 0) & (idx32[3] == 0) & (idx32[5] == 0) & (idx32[7] == 0);
    const long long* idx64 = (const long long*)idxp;

    for (int it = 0; it < 32; ++it) {
        int r = it * 4 + w;
        long long base = (long long)(n0 + r) * 4 + cu_col;
        long long cu = is64 ? idx64[base]     : (long long)idx32[base];
        long long cv = is64 ? idx64[base + 1] : (long long)idx32[base + 1];
        uT[lane * PADA + r] = concepts[cu * 32 + lane];
        vT[lane * PADA + r] = concepts[cv * 32 + lane];
    }
    __syncthreads();

    if (leftside) {
        float wn[32];
        #pragma unroll
        for (int i2 = 0; i2 < 32; ++i2) wn[i2] = Wn[i2 * 32 + lane];
        float bnk = bn[lane];
        for (int rr = 0; rr < 32; ++rr) {
            int r = (w << 5) + rr;
            float na = bnk;
            #pragma unroll
            for (int i2 = 0; i2 < 32; ++i2)
                na = fmaf(uT[i2 * PADA + r], wn[i2], na);
            __syncwarp();
            uT[lane * PADA + r] = na;
            __syncwarp();
        }
    }
    __syncthreads();

    int tc = tid & 7, tr = tid >> 3;
    int c0 = tc << 2, r0 = tr << 3;
    ull acc[4][4];
    #pragma unroll
    for (int p = 0; p < 4; ++p)
        #pragma unroll
        for (int c = 0; c < 4; ++c) acc[p][c] = 0ull;

    for (int s = 0; s < 34; ++s) {
        cpa_wait<1>();
        __syncthreads();
        if (s + 2 < 34) {
            #pragma unroll
            for (int q = 0; q < 2; ++q)
                cpa16(bs_base + (((s + 2) % 3) * 1024 + (e0 + q) * 4) * 4,
                      Wa + (size_t)(s + 2) * 1024 + (e0 + q) * 4);
        }
        cpa_commit();

        const float* Bc = Bs + (s % 3) * 1024;

        if (s >= 2) {
            int ii = s - 2;
            ull qa[4][4];
            #pragma unroll
            for (int kk = 0; kk < 32; ++kk) {
                float4 ra = *(const float4*)&vT[kk * PADA + r0];
                float4 rb = *(const float4*)&vT[kk * PADA + r0 + 4];
                ull rp[4] = { ((const ull*)&ra)[0], ((const ull*)&ra)[1],
                              ((const ull*)&rb)[0], ((const ull*)&rb)[1] };
                float4 bv = *(const float4*)&Bc[(kk << 5) + c0];
                ull bd[4] = { pk2(bv.x), pk2(bv.y), pk2(bv.z), pk2(bv.w) };
                if (kk == 0) {
                    #pragma unroll
                    for (int p = 0; p < 4; ++p)
                        #pragma unroll
                        for (int c = 0; c < 4; ++c)
                            qa[p][c] = mul2(rp[p], bd[c]);
                } else {
                    #pragma unroll
                    for (int p = 0; p < 4; ++p)
                        #pragma unroll
                        for (int c = 0; c < 4; ++c)
                            fma2(qa[p][c], rp[p], bd[c]);
                }
            }
            float4 ua = *(const float4*)&uT[ii * PADA + r0];
            float4 ub = *(const float4*)&uT[ii * PADA + r0 + 4];
            ull up[4] = { ((const ull*)&ua)[0], ((const ull*)&ua)[1],
                          ((const ull*)&ub)[0], ((const ull*)&ub)[1] };
            #pragma unroll
            for (int p = 0; p < 4; ++p)
                #pragma unroll
                for (int c = 0; c < 4; ++c)
                    fma2(acc[p][c], up[p], qa[p][c]);
        } else {
            const float* S = (s == 0) ? uT : vT;
            #pragma unroll
            for (int kk = 0; kk < 32; ++kk) {
                float4 ra = *(const float4*)&S[kk * PADA + r0];
                float4 rb = *(const float4*)&S[kk * PADA + r0 + 4];
                ull rp[4] = { ((const ull*)&ra)[0], ((const ull*)&ra)[1],
                              ((const ull*)&rb)[0], ((const ull*)&rb)[1] };
                float4 bv = *(const float4*)&Bc[(kk << 5) + c0];
                ull bd[4] = { pk2(bv.x), pk2(bv.y), pk2(bv.z), pk2(bv.w) };
                #pragma unroll
                for (int p = 0; p < 4; ++p)
                    #pragma unroll
                    for (int c = 0; c < 4; ++c)
                        fma2(acc[p][c], rp[p], bd[c]);
            }
        }
    }

    float4 bav = *(const float4*)&ba[c0];
    int hoff = leftside ? 0 : 32;
    #pragma unroll
    for (int p = 0; p < 4; ++p) {
        float2 v0 = up2(acc[p][0]);
        float2 v1 = up2(acc[p][1]);
        float2 v2 = up2(acc[p][2]);
        float2 v3 = up2(acc[p][3]);
        float4 oA = { v0.x + bav.x, v1.x + bav.y, v2.x + bav.z, v3.x + bav.w };
        float4 oB = { v0.y + bav.x, v1.y + bav.y, v2.y + bav.z, v3.y + bav.w };
        *(float4*)&g_lr[(size_t)(n0 + r0 + 2 * p)     * 64 + hoff + c0] = oA;
        *(float4*)&g_lr[(size_t)(n0 + r0 + 2 * p + 1) * 64 + hoff + c0] = oB;
    }
}

// =====================================================================
// Kernel B: raw mma.sync bf16 hi/lo split. 128 rows x 128 cols per CTA.
// 512 threads; warp grid 4M x 4N; warp tile 32x32 (2 mt x 4 nt).
// =====================================================================
#define SM_LR   0             // float[128*64]                    32768
#define SM_AHI  32768         // bf16[128][64] swizzled           16384
#define SM_ALO  49152         // bf16[128][64] swizzled           16384
#define SM_B    65536         // 3 x (hi 16384 + lo 16384)        98304
#define SM_BS1  163840        // float[128]
#define SM_W2   164352        // float[128]
#define SM_DS   164864        // float[128][4]
#define KM_SMEM 166912

__global__ __launch_bounds__(512, 1) void k_main(
    const float* __restrict__ bs1, const float* __restrict__ Ws2,
    const float* __restrict__ bs2, float* __restrict__ out)
{
    extern __shared__ __align__(16) char sm[];
    float* LR = (float*)(sm + SM_LR);
    uint32_t sb = s2u(sm);
    int tid = threadIdx.x;
    int wid = tid >> 5, lane = tid & 31;
    int n0 = blockIdx.x << 7;

    // prefetch B chunks 0,1 (32KB each: 2048 x 16B)
    #pragma unroll
    for (int p = 0; p < 2; ++p) {
        #pragma unroll
        for (int q = 0; q < 2; ++q) {
            int e = q * 512 + tid;   // 1024 per half
            cpa16(sb + SM_B + p * 32768 + e * 16,         (const char*)g_whi + (size_t)p * 16384 + e * 16);
            cpa16(sb + SM_B + p * 32768 + 16384 + e * 16, (const char*)g_wlo + (size_t)p * 16384 + e * 16);
        }
        cpa_commit();
    }

    #pragma unroll
    for (int it = 0; it < 4; ++it) {
        int e4 = it * 512 + tid;
        int r = e4 >> 4, q = e4 & 15;
        *(float4*)&LR[r * 64 + q * 4] = *(const float4*)&g_lr[(size_t)(n0 + r) * 64 + q * 4];
    }
    if (tid < 128) {
        ((float*)(sm + SM_BS1))[tid] = bs1[tid];
        ((float*)(sm + SM_W2))[tid]  = Ws2[tid];
    }
    __syncthreads();

    float acc[2][4][4];
    #pragma unroll
    for (int mt = 0; mt < 2; ++mt)
        #pragma unroll
        for (int nt = 0; nt < 4; ++nt)
            #pragma unroll
            for (int e = 0; e < 4; ++e) acc[mt][nt][e] = 0.f;

    int m0w = (wid >> 2) * 32, n0w = (wid & 3) * 32;
    // ldmatrix lane geometry
    int li = lane & 7, lt = lane >> 3;           // tile index within x4
    int rA_off = li + ((lt & 1) << 3);           // A: row within 16-row tile
    int segA_h = lt >> 1;                        // A: k-seg half
    int hB = lt & 1;                             // B: k-seg half
    int lobB = (lt >> 1) * 16384;                // B: lanes 16-31 -> lo buffer

    for (int s = 0; s < 17; ++s) {
        // materialize feature chunk s into Ahi/Alo (pairs; swizzled)
        #pragma unroll
        for (int it = 0; it < 8; ++it) {
            int p = it * 512 + tid;              // 4096 pairs
            int row = p >> 5, t0 = (p & 31) * 2;
            float f0, f1;
            if (s == 0) {
                float2 lv = *(const float2*)&LR[row * 64 + t0];
                f0 = lv.x; f1 = lv.y;
            } else {
                int i = 2 * (s - 1) + (t0 >> 5), j = t0 & 31;
                float Lv = LR[row * 64 + i];
                float2 rv = *(const float2*)&LR[row * 64 + 32 + j];
                f0 = Lv * rv.x;
                f1 = Lv * rv.y;
            }
            uint32_t hp;
            asm("cvt.rn.bf16x2.f32 %0, %1, %2;" : "=r"(hp) : "f"(f1), "f"(f0));
            float b0 = __uint_as_float(hp << 16);
            float b1 = __uint_as_float(hp & 0xffff0000u);
            float l0 = f0 - b0, l1 = f1 - b1;
            uint32_t lp;
            asm("cvt.rn.bf16x2.f32 %0, %1, %2;" : "=r"(lp) : "f"(l1), "f"(l0));
            uint32_t off = row * 128 + ((((t0 >> 3) ^ (row & 7))) << 4) + (t0 & 7) * 2;
            *(uint32_t*)(sm + SM_AHI + off) = hp;
            *(uint32_t*)(sm + SM_ALO + off) = lp;
        }
        cpa_wait<1>();
        __syncthreads();                         // A visible + B chunk s visible

        if (s + 2 < 17) {
            #pragma unroll
            for (int q = 0; q < 2; ++q) {
                int e = q * 512 + tid;
                cpa16(sb + SM_B + ((s + 2) % 3) * 32768 + e * 16,
                      (const char*)g_whi + (size_t)(s + 2) * 16384 + e * 16);
                cpa16(sb + SM_B + ((s + 2) % 3) * 32768 + 16384 + e * 16,
                      (const char*)g_wlo + (size_t)(s + 2) * 16384 + e * 16);
            }
        }
        cpa_commit();

        uint32_t Bb = sb + SM_B + (s % 3) * 32768;
        #pragma unroll
        for (int ks = 0; ks < 4; ++ks) {
            // B fragments: one ldsm4 per nt; lanes 0-15 hi, 16-31 lo
            uint32_t bf[4][4];
            #pragma unroll
            for (int nt = 0; nt < 4; ++nt) {
                int row = n0w + nt * 8 + li;
                uint32_t addr = Bb + lobB + row * 128 + ((((2 * ks + hB) ^ (row & 7))) << 4);
                ldsm4(bf[nt], addr);
            }
            #pragma unroll
            for (int mt = 0; mt < 2; ++mt) {
                int row = m0w + mt * 16 + rA_off;
                int seg = 2 * ks + segA_h;
                uint32_t addr = sb + SM_AHI + row * 128 + (((seg ^ (row & 7))) << 4);
                uint32_t ah[4], al[4];
                ldsm4(ah, addr);
                ldsm4(al, addr + 16384);
                #pragma unroll
                for (int nt = 0; nt < 4; ++nt) {
                    mma_bf16(acc[mt][nt], ah, bf[nt]);          // hi*hi
                    mma_bf16(acc[mt][nt], ah, bf[nt] + 2);      // hi*lo
                    mma_bf16(acc[mt][nt], al, bf[nt]);          // lo*hi
                }
            }
        }
        __syncthreads();                         // A consumed; safe to overwrite
    }

    // epilogue: +bs1, elu, dot Ws2, reduce
    const float* bs1s = (const float*)(sm + SM_BS1);
    const float* w2s  = (const float*)(sm + SM_W2);
    float* Dsum = (float*)(sm + SM_DS);
    int q = lane >> 2, c2 = (lane & 3) * 2;
    float bias2 = bs2[0];
    #pragma unroll
    for (int mt = 0; mt < 2; ++mt) {
        float s0 = 0.f, s1 = 0.f;
        #pragma unroll
        for (int nt = 0; nt < 4; ++nt) {
            int col = n0w + nt * 8 + c2;
            float2 bv = *(const float2*)&bs1s[col];
            float2 wv = *(const float2*)&w2s[col];
            float* d = acc[mt][nt];
            float x0 = d[0] + bv.x, x1 = d[1] + bv.y;
            float x2 = d[2] + bv.x, x3 = d[3] + bv.y;
            float h0 = x0 > 0.f ? x0 : expm1f(x0);
            float h1 = x1 > 0.f ? x1 : expm1f(x1);
            float h2 = x2 > 0.f ? x2 : expm1f(x2);
            float h3 = x3 > 0.f ? x3 : expm1f(x3);
            s0 = fmaf(h0, wv.x, fmaf(h1, wv.y, s0));
            s1 = fmaf(h2, wv.x, fmaf(h3, wv.y, s1));
        }
        s0 += __shfl_xor_sync(0xffffffffu, s0, 1);
        s0 += __shfl_xor_sync(0xffffffffu, s0, 2);
        s1 += __shfl_xor_sync(0xffffffffu, s1, 1);
        s1 += __shfl_xor_sync(0xffffffffu, s1, 2);
        if ((lane & 3) == 0) {
            int row = m0w + mt * 16 + q;
            Dsum[row * 4 + (wid & 3)] = s0;
            Dsum[(row + 8) * 4 + (wid & 3)] = s1;
        }
    }
    __syncthreads();
    if (tid < 128) {
        float v = Dsum[tid * 4] + Dsum[tid * 4 + 1] + Dsum[tid * 4 + 2] + Dsum[tid * 4 + 3];
        out[n0 + tid] = v + bias2;
    }
}

extern "C" void kernel_launch(void* const* d_in, const int* in_sizes, int n_in,
                              void* d_out, int out_size)
{
    const float* concepts = (const float*)d_in[0];
    const float* Wn  = (const float*)d_in[1];
    const float* bn  = (const float*)d_in[2];
    const float* Wa  = (const float*)d_in[3];
    const float* ba  = (const float*)d_in[4];
    const float* Ws1 = (const float*)d_in[5];
    const float* bs1 = (const float*)d_in[6];
    const float* Ws2 = (const float*)d_in[7];
    const float* bs2 = (const float*)d_in[8];
    const void*  idx = d_in[9];
    int nrows = in_sizes[9] / 4;

    static int inited = 0;
    if (!inited) {
        cudaFuncSetAttribute(k_main, cudaFuncAttributeMaxDynamicSharedMemorySize, KM_SMEM);
        inited = 1;
    }

    k_conv<<<(17 * 64 * 128 + 255) / 256, 256>>>(Ws1);
    k_lr<<<(nrows / 128) * 2, 128>>>(concepts, Wn, bn, Wa, ba, idx, nrows);
    k_main<<<nrows / 128, 512, KM_SMEM>>>(bs1, Ws2, bs2, (float*)d_out);
}